// round 17
// baseline (speedup 1.0000x reference)
#include <cuda_runtime.h>
#include <cstdint>
#include <math.h>

#define T_STEPS 250
#define NN      256
#define IN_DIM  1024
#define HH      1024
#define OUT_DIM 35
#define BR      4
#define INB     256
#define TC      25
#define NCHUNK  (T_STEPS / TC)     // 10
#define MC      (TC * NN)          // 6400 rows per chunk

// Persistent state (device globals: no allocation allowed)
__device__ float g_state[NN * BR * HH];
__device__ float g_v1[NN * HH];
__device__ float g_alpha[BR * HH];
__device__ float g_v2[NN * OUT_DIM];
__device__ float g_acc[NN * OUT_DIM];
__device__ float g_Y[2][(size_t)MC * BR * HH];   // double-buffered chunk output
__device__ uint4 g_mask[TC * NN * 8];            // spike bitmasks: [t][n][warpchunk]

__global__ void init_kernel(const float* __restrict__ taus) {
    int idx = blockIdx.x * blockDim.x + threadIdx.x;
    g_state[idx] = 0.f;
    if (idx < NN * HH) g_v1[idx] = 0.f;
    if (idx < BR * HH) g_alpha[idx] = 1.f / (1.f + expf(-taus[idx]));
    if (idx < NN * OUT_DIM) { g_v2[idx] = 0.f; g_acc[idx] = 0.f; }
}

// ---------------------------------------------------------------------------
// Batched branch GEMM (unchanged; at RF-bank hardware floor)
// ---------------------------------------------------------------------------
__global__ __launch_bounds__(256, 1) void gemm_kernel(
    const float* __restrict__ Xc,
    const float* __restrict__ Wb,
    const float* __restrict__ bb,
    int ybuf)
{
    __shared__ float As[2][16][256];
    __shared__ float Bs[2][16][128];

    const int tid  = threadIdx.x;
    const int h0v  = blockIdx.x * 128;
    const int m0   = blockIdx.y * 256;
    const int br   = blockIdx.z;

    const int tx = tid & 15;
    const int ty = tid >> 4;
    const int mB = ty * 16;
    const int hB = tx * 8;

    const float* aptr = Xc + (size_t)(m0 + tid) * IN_DIM + br * INB;
    const int bk = tid >> 4, bh = (tid & 15) * 8;
    const float* bptr = Wb + ((size_t)br * INB + bk) * HH + h0v + bh;

    float* Yb = g_Y[ybuf];

    unsigned long long acc[8][8];
#pragma unroll
    for (int i = 0; i < 8; ++i)
#pragma unroll
        for (int j = 0; j < 8; ++j) acc[i][j] = 0ULL;

    {
        float4 a0 = *(const float4*)(aptr + 0);
        float4 a1 = *(const float4*)(aptr + 4);
        float4 a2 = *(const float4*)(aptr + 8);
        float4 a3 = *(const float4*)(aptr + 12);
        float4 b0 = *(const float4*)(bptr);
        float4 b1 = *(const float4*)(bptr + 4);
        As[0][ 0][tid] = a0.x; As[0][ 1][tid] = a0.y;
        As[0][ 2][tid] = a0.z; As[0][ 3][tid] = a0.w;
        As[0][ 4][tid] = a1.x; As[0][ 5][tid] = a1.y;
        As[0][ 6][tid] = a1.z; As[0][ 7][tid] = a1.w;
        As[0][ 8][tid] = a2.x; As[0][ 9][tid] = a2.y;
        As[0][10][tid] = a2.z; As[0][11][tid] = a2.w;
        As[0][12][tid] = a3.x; As[0][13][tid] = a3.y;
        As[0][14][tid] = a3.z; As[0][15][tid] = a3.w;
        *(float4*)&Bs[0][bk][bh]     = b0;
        *(float4*)&Bs[0][bk][bh + 4] = b1;
    }
    __syncthreads();

    int buf = 0;
#pragma unroll 1
    for (int k0 = 0; k0 < INB; k0 += 16) {
        const bool more = (k0 + 16) < INB;
        float4 na0, na1, na2, na3, nb0, nb1;
        if (more) {
            na0 = *(const float4*)(aptr + k0 + 16);
            na1 = *(const float4*)(aptr + k0 + 20);
            na2 = *(const float4*)(aptr + k0 + 24);
            na3 = *(const float4*)(aptr + k0 + 28);
            nb0 = *(const float4*)(bptr + (size_t)(k0 + 16) * HH);
            nb1 = *(const float4*)(bptr + (size_t)(k0 + 16) * HH + 4);
        }
#pragma unroll
        for (int k = 0; k < 16; ++k) {
            ulonglong2 aq0 = *(const ulonglong2*)&As[buf][k][mB];
            ulonglong2 aq1 = *(const ulonglong2*)&As[buf][k][mB + 4];
            ulonglong2 aq2 = *(const ulonglong2*)&As[buf][k][mB + 8];
            ulonglong2 aq3 = *(const ulonglong2*)&As[buf][k][mB + 12];
            unsigned long long a2p[8] = {aq0.x, aq0.y, aq1.x, aq1.y,
                                         aq2.x, aq2.y, aq3.x, aq3.y};
            float4 bf0 = *(const float4*)&Bs[buf][k][hB];
            float4 bf1 = *(const float4*)&Bs[buf][k][hB + 4];
            float bv[8] = {bf0.x, bf0.y, bf0.z, bf0.w,
                           bf1.x, bf1.y, bf1.z, bf1.w};
            unsigned long long bd[8];
#pragma unroll
            for (int j = 0; j < 8; ++j)
                asm("mov.b64 %0, {%1, %1};" : "=l"(bd[j]) : "f"(bv[j]));
#pragma unroll
            for (int i = 0; i < 8; ++i)
#pragma unroll
                for (int j = 0; j < 8; ++j)
                    asm("fma.rn.f32x2 %0, %1, %2, %0;"
                        : "+l"(acc[i][j]) : "l"(a2p[i]), "l"(bd[j]));
        }
        if (more) {
            const int nb = buf ^ 1;
            As[nb][ 0][tid] = na0.x; As[nb][ 1][tid] = na0.y;
            As[nb][ 2][tid] = na0.z; As[nb][ 3][tid] = na0.w;
            As[nb][ 4][tid] = na1.x; As[nb][ 5][tid] = na1.y;
            As[nb][ 6][tid] = na1.z; As[nb][ 7][tid] = na1.w;
            As[nb][ 8][tid] = na2.x; As[nb][ 9][tid] = na2.y;
            As[nb][10][tid] = na2.z; As[nb][11][tid] = na2.w;
            As[nb][12][tid] = na3.x; As[nb][13][tid] = na3.y;
            As[nb][14][tid] = na3.z; As[nb][15][tid] = na3.w;
            *(float4*)&Bs[nb][bk][bh]     = nb0;
            *(float4*)&Bs[nb][bk][bh + 4] = nb1;
            __syncthreads();
            buf = nb;
        }
    }

    float4 bias0 = *(const float4*)(bb + br * HH + h0v + hB);
    float4 bias1 = *(const float4*)(bb + br * HH + h0v + hB + 4);
    const float bvv[8] = {bias0.x, bias0.y, bias0.z, bias0.w,
                          bias1.x, bias1.y, bias1.z, bias1.w};
#pragma unroll
    for (int i = 0; i < 8; ++i) {
        float lo[8], hi[8];
#pragma unroll
        for (int j = 0; j < 8; ++j)
            asm("mov.b64 {%0, %1}, %2;" : "=f"(lo[j]), "=f"(hi[j]) : "l"(acc[i][j]));
        size_t r0 = (size_t)(m0 + mB + 2 * i);
        float* yp0 = &Yb[(r0 * BR + br) * HH + h0v + hB];
        float* yp1 = yp0 + (size_t)BR * HH;
        float4 w;
        w.x = lo[0] + bvv[0]; w.y = lo[1] + bvv[1];
        w.z = lo[2] + bvv[2]; w.w = lo[3] + bvv[3];
        *(float4*)yp0 = w;
        w.x = lo[4] + bvv[4]; w.y = lo[5] + bvv[5];
        w.z = lo[6] + bvv[6]; w.w = lo[7] + bvv[7];
        *(float4*)(yp0 + 4) = w;
        w.x = hi[0] + bvv[0]; w.y = hi[1] + bvv[1];
        w.z = hi[2] + bvv[2]; w.w = hi[3] + bvv[3];
        *(float4*)yp1 = w;
        w.x = hi[4] + bvv[4]; w.y = hi[5] + bvv[5];
        w.z = hi[6] + bvv[6]; w.w = hi[7] + bvv[7];
        *(float4*)(yp1 + 4) = w;
    }
}

// ---------------------------------------------------------------------------
// Kernel A: dendritic integration + LIF1, barrier-free, spikes -> bitmasks.
// One thread per (n, 4 h). 256 blocks x 256 threads.
// ---------------------------------------------------------------------------
__global__ __launch_bounds__(256) void lifA_kernel(
    const float* __restrict__ tau1p, int ybuf)
{
    const int g   = blockIdx.x * 256 + threadIdx.x;   // 0..65535
    const int n   = g >> 8;
    const int hq  = g & 255;
    const int h0  = hq * 4;
    const int lane = threadIdx.x & 31;
    const int wIn = hq >> 5;                          // 0..7 warp-chunk within n

    const float4* yb4 = (const float4*)(g_Y[ybuf] + ((size_t)n * BR) * HH + h0);
    const size_t ystep = (size_t)NN * BR * HH / 4;
    const size_t bstep = HH / 4;

    float4 st[BR], al[BR];
#pragma unroll
    for (int b = 0; b < BR; ++b) {
        st[b] = *(float4*)&g_state[((size_t)n * BR + b) * HH + h0];
        al[b] = *(const float4*)&g_alpha[b * HH + h0];
    }
    float4 v1 = *(float4*)&g_v1[(size_t)n * HH + h0];
    const float tau1v = *tau1p;

    float4 ycur[BR], ynxt[BR];
#pragma unroll
    for (int b = 0; b < BR; ++b) ycur[b] = __ldg(yb4 + b * bstep);

#pragma unroll 1
    for (int t = 0; t < TC; ++t) {
        if (t + 1 < TC) {
            const float4* yp = yb4 + (size_t)(t + 1) * ystep;
#pragma unroll
            for (int b = 0; b < BR; ++b) ynxt[b] = __ldg(yp + b * bstep);
        }
        float4 cb = {0.f, 0.f, 0.f, 0.f};
#pragma unroll
        for (int b = 0; b < BR; ++b) {
            st[b].x = al[b].x * st[b].x + (1.f - al[b].x) * ycur[b].x;
            st[b].y = al[b].y * st[b].y + (1.f - al[b].y) * ycur[b].y;
            st[b].z = al[b].z * st[b].z + (1.f - al[b].z) * ycur[b].z;
            st[b].w = al[b].w * st[b].w + (1.f - al[b].w) * ycur[b].w;
            cb.x += st[b].x; cb.y += st[b].y; cb.z += st[b].z; cb.w += st[b].w;
        }
        v1.x = v1.x + (cb.x - v1.x) / tau1v;
        v1.y = v1.y + (cb.y - v1.y) / tau1v;
        v1.z = v1.z + (cb.z - v1.z) / tau1v;
        v1.w = v1.w + (cb.w - v1.w) / tau1v;
        unsigned m0 = __ballot_sync(0xffffffffu, v1.x >= 1.f);
        unsigned m1 = __ballot_sync(0xffffffffu, v1.y >= 1.f);
        unsigned m2 = __ballot_sync(0xffffffffu, v1.z >= 1.f);
        unsigned m3 = __ballot_sync(0xffffffffu, v1.w >= 1.f);
        if (v1.x >= 1.f) v1.x = 0.f;
        if (v1.y >= 1.f) v1.y = 0.f;
        if (v1.z >= 1.f) v1.z = 0.f;
        if (v1.w >= 1.f) v1.w = 0.f;
        if (lane == 0)
            g_mask[((size_t)t * NN + n) * 8 + wIn] = make_uint4(m0, m1, m2, m3);
#pragma unroll
        for (int b = 0; b < BR; ++b) ycur[b] = ynxt[b];
    }

#pragma unroll
    for (int b = 0; b < BR; ++b)
        *(float4*)&g_state[((size_t)n * BR + b) * HH + h0] = st[b];
    *(float4*)&g_v1[(size_t)n * HH + h0] = v1;
}

// ---------------------------------------------------------------------------
// Kernel B: output GEMM (spike-gated, warp-cooperative o-major) + LIF2 + acc.
// 128 blocks x 512 threads; block owns 2 n; warp owns 128 h of one n.
// ---------------------------------------------------------------------------
#define PROC_WORD(mword, kk)                                                  \
    {                                                                         \
        unsigned m = (mword);                                                 \
        while (m) {                                                           \
            int l = __ffs(m) - 1; m &= m - 1;                                 \
            const float* wr = W2 + (size_t)(hb + l * 4 + (kk)) * OUT_DIM;     \
            a0 += __ldg(wr + lane);                                           \
            if (lane < 3) a1 += __ldg(wr + 32 + lane);                        \
        }                                                                     \
    }

__global__ __launch_bounds__(512) void lifB_kernel(
    const float* __restrict__ W2,
    const float* __restrict__ b2,
    const float* __restrict__ tau2p)
{
    __shared__ float red2[2][8][36];

    const int tid  = threadIdx.x;
    const int wid  = tid >> 5, lane = tid & 31;
    const int n_l  = wid >> 3, wIn = wid & 7;
    const int n    = blockIdx.x * 2 + n_l;
    const int hb   = wIn * 128;
    const float tau2v = *tau2p;

    const bool own = (tid < 2 * OUT_DIM);
    const int o_o = tid % OUT_DIM, n_o = tid / OUT_DIM;
    float v2 = 0.f, accv = 0.f, b2v = 0.f;
    int vidx = 0;
    if (own) {
        vidx = (blockIdx.x * 2 + n_o) * OUT_DIM + o_o;
        v2 = g_v2[vidx]; accv = g_acc[vidx]; b2v = b2[o_o];
    }

    uint4 W = __ldg(&g_mask[(size_t)n * 8 + wIn]);   // t = 0

#pragma unroll 1
    for (int t = 0; t < TC; ++t) {
        uint4 Wn;
        if (t + 1 < TC)
            Wn = __ldg(&g_mask[((size_t)(t + 1) * NN + n) * 8 + wIn]);

        float a0 = 0.f, a1 = 0.f;
        PROC_WORD(W.x, 0)
        PROC_WORD(W.y, 1)
        PROC_WORD(W.z, 2)
        PROC_WORD(W.w, 3)

        red2[n_l][wIn][lane] = a0;
        if (lane < 3) red2[n_l][wIn][32 + lane] = a1;
        __syncthreads();

        if (own) {
            float s = b2v;
#pragma unroll
            for (int w = 0; w < 8; ++w) s += red2[n_o][w][o_o];
            v2 = v2 + (s - v2) / tau2v;
            float sp = (v2 >= 1.f) ? 1.f : 0.f;
            v2 *= (1.f - sp);
            accv += sp;
        }
        __syncthreads();
        W = Wn;
    }

    if (own) { g_v2[vidx] = v2; g_acc[vidx] = accv; }
}

// ---------------------------------------------------------------------------
// Final log_softmax
// ---------------------------------------------------------------------------
__global__ void final_kernel(float* __restrict__ out) {
    const int n = threadIdx.x;
    float f[OUT_DIM];
    float m = -1e30f;
#pragma unroll
    for (int o = 0; o < OUT_DIM; ++o) {
        f[o] = g_acc[n * OUT_DIM + o];
        m = fmaxf(m, f[o]);
    }
    float s = 0.f;
#pragma unroll
    for (int o = 0; o < OUT_DIM; ++o) s += expf(f[o] - m);
    float l = logf(s);
#pragma unroll
    for (int o = 0; o < OUT_DIM; ++o) out[n * OUT_DIM + o] = f[o] - m - l;
}

extern "C" void kernel_launch(void* const* d_in, const int* in_sizes, int n_in,
                              void* d_out, int out_size) {
    const float* x    = (const float*)d_in[0];
    const float* Wb   = (const float*)d_in[1];
    const float* bb   = (const float*)d_in[2];
    const float* taus = (const float*)d_in[3];
    const float* W2   = (const float*)d_in[4];
    const float* b2   = (const float*)d_in[5];
    const float* tau1 = (const float*)d_in[6];
    const float* tau2 = (const float*)d_in[7];
    float* out = (float*)d_out;

    static cudaStream_t s2 = nullptr;
    static cudaEvent_t evG[NCHUNK], evA[NCHUNK], evB[NCHUNK];
    if (!s2) {
        cudaStreamCreateWithFlags(&s2, cudaStreamNonBlocking);
        for (int i = 0; i < NCHUNK; ++i) {
            cudaEventCreateWithFlags(&evG[i], cudaEventDisableTiming);
            cudaEventCreateWithFlags(&evA[i], cudaEventDisableTiming);
            cudaEventCreateWithFlags(&evB[i], cudaEventDisableTiming);
        }
    }

    init_kernel<<<4096, 256>>>(taus);

    dim3 ggrid(HH / 128, MC / 256, BR);   // (8, 25, 4) = 800 blocks
    for (int c = 0; c < NCHUNK; ++c) {
        const float* Xc = x + (size_t)c * MC * IN_DIM;
        const int yb = c & 1;
        // gemm(c) overwrites g_Y[yb]; lifA(c-2) was its last reader
        if (c >= 2) cudaStreamWaitEvent(0, evA[c - 2], 0);
        gemm_kernel<<<ggrid, 256>>>(Xc, Wb, bb, yb);
        cudaEventRecord(evG[c], 0);
        cudaStreamWaitEvent(s2, evG[c], 0);
        lifA_kernel<<<256, 256, 0, s2>>>(tau1, yb);
        cudaEventRecord(evA[c], s2);
        lifB_kernel<<<128, 512, 0, s2>>>(W2, b2, tau2);
        cudaEventRecord(evB[c], s2);
    }
    cudaStreamWaitEvent(0, evB[NCHUNK - 1], 0);
    final_kernel<<<1, 256>>>(out);
}